// round 3
// baseline (speedup 1.0000x reference)
#include <cuda_runtime.h>
#include <cuda_bf16.h>
#include <math.h>

#define N   4096
#define D   128
#define H   2
#define DH  64
#define FF  256
#define NE  2048
#define NNZ 65536
#define EPS 1e-5f

// ---------------- scratch (no allocation allowed) ----------------
__device__ float g_h[N * D];
__device__ float g_q[N * D];
__device__ float g_k[N * D];
__device__ float g_v[N * D];
__device__ float g_o[N * D];
__device__ float g_t[N * D];
__device__ float g_z[N * FF];
__device__ float g_e[NE * D];
__device__ float g_bdeg[NE];
__device__ float g_ddeg[N];
__device__ int   g_edge_is64;

// ---------------- edge dtype detection ----------------
// int64 little-endian with values < 2^31 => every odd 32-bit word is 0.
__global__ void detect_edge_kernel(const int* __restrict__ e32)
{
    if (threadIdx.x == 0 && blockIdx.x == 0) {
        int is64 = 1;
        #pragma unroll
        for (int i = 1; i < 64; i += 2)
            if (e32[i] != 0) is64 = 0;
        g_edge_is64 = is64;
    }
}

__device__ __forceinline__ int2 load_edge(const void* __restrict__ edge, int nz)
{
    if (g_edge_is64) {
        const long long* e = (const long long*)edge;
        return make_int2((int)e[nz], (int)e[NNZ + nz]);
    } else {
        const int* e = (const int*)edge;
        return make_int2(e[nz], e[NNZ + nz]);
    }
}

// ---------------- generic tiled SGEMM: C = act(A @ B + bias) ----------------
__global__ void sgemm_bias_act(const float* __restrict__ A, const float* __restrict__ B,
                               const float* __restrict__ bias, float* __restrict__ C,
                               int M, int Nc, int K, int act)
{
    __shared__ float As[16][64];   // [k][m]
    __shared__ float Bs[16][64];   // [k][n]
    int tid = threadIdx.x;            // 256 threads
    int tx = tid & 15, ty = tid >> 4; // 16x16
    int row0 = blockIdx.y * 64, col0 = blockIdx.x * 64;

    float acc[4][4] = {};
    for (int k0 = 0; k0 < K; k0 += 16) {
        #pragma unroll
        for (int i = tid; i < 64 * 16; i += 256) {
            int m = i >> 4, kk = i & 15;
            As[kk][m] = A[(size_t)(row0 + m) * K + k0 + kk];
        }
        #pragma unroll
        for (int i = tid; i < 16 * 64; i += 256) {
            int kk = i >> 6, n = i & 63;
            Bs[kk][n] = B[(size_t)(k0 + kk) * Nc + col0 + n];
        }
        __syncthreads();
        #pragma unroll
        for (int kk = 0; kk < 16; kk++) {
            float a[4], b[4];
            #pragma unroll
            for (int i = 0; i < 4; i++) a[i] = As[kk][ty * 4 + i];
            #pragma unroll
            for (int j = 0; j < 4; j++) b[j] = Bs[kk][tx * 4 + j];
            #pragma unroll
            for (int i = 0; i < 4; i++)
                #pragma unroll
                for (int j = 0; j < 4; j++) acc[i][j] = fmaf(a[i], b[j], acc[i][j]);
        }
        __syncthreads();
    }
    #pragma unroll
    for (int i = 0; i < 4; i++) {
        int r = row0 + ty * 4 + i;
        #pragma unroll
        for (int j = 0; j < 4; j++) {
            int c = col0 + tx * 4 + j;
            float val = acc[i][j] + (bias ? bias[c] : 0.0f);
            if (act == 1) val = 1.0f / (1.0f + __expf(-val));
            C[(size_t)r * Nc + c] = val;
        }
    }
}

// ---------------- flash attention, fp32, BM=BN=64, DH=64 ----------------
#define FPAD 65
__global__ void flash_attn(const float* __restrict__ q, const float* __restrict__ k,
                           const float* __restrict__ v, float* __restrict__ o)
{
    extern __shared__ float fsm[];
    float* Qs = fsm;                 // [d][r]  64x65
    float* Ks = Qs + 64 * FPAD;      // [d][c]
    float* Vs = Ks + 64 * FPAD;      // [j][c]
    float* Ps = Vs + 64 * FPAD;      // [r][j]

    int tid = threadIdx.x;            // 256
    int tx = tid & 15, ty = tid >> 4;
    int qrow0 = blockIdx.x * 64;
    int hcol  = blockIdx.y * DH;

    #pragma unroll
    for (int i = tid; i < 64 * 64; i += 256) {
        int r = i >> 6, d = i & 63;
        Qs[d * FPAD + r] = q[(size_t)(qrow0 + r) * D + hcol + d];
    }

    float m_i[4], l_i[4], acc[4][4] = {};
    #pragma unroll
    for (int i = 0; i < 4; i++) { m_i[i] = -1e30f; l_i[i] = 0.0f; }
    const float scale = 0.125f;  // 1/sqrt(64)

    for (int kb = 0; kb < N; kb += 64) {
        __syncthreads();
        #pragma unroll
        for (int i = tid; i < 64 * 64; i += 256) {
            int c = i >> 6, d = i & 63;
            float kv = k[(size_t)(kb + c) * D + hcol + d];
            float vv = v[(size_t)(kb + c) * D + hcol + d];
            Ks[d * FPAD + c] = kv;
            Vs[c * FPAD + d] = vv;
        }
        __syncthreads();

        // S = Q @ K^T
        float s[4][4] = {};
        #pragma unroll
        for (int d = 0; d < 64; d++) {
            float a[4], b[4];
            #pragma unroll
            for (int i = 0; i < 4; i++) a[i] = Qs[d * FPAD + ty * 4 + i];
            #pragma unroll
            for (int j = 0; j < 4; j++) b[j] = Ks[d * FPAD + tx * 4 + j];
            #pragma unroll
            for (int i = 0; i < 4; i++)
                #pragma unroll
                for (int j = 0; j < 4; j++) s[i][j] = fmaf(a[i], b[j], s[i][j]);
        }

        // online softmax (16-lane row groups share ty)
        #pragma unroll
        for (int i = 0; i < 4; i++) {
            float s0 = s[i][0] * scale, s1 = s[i][1] * scale;
            float s2 = s[i][2] * scale, s3 = s[i][3] * scale;
            float mt = fmaxf(fmaxf(s0, s1), fmaxf(s2, s3));
            #pragma unroll
            for (int off = 8; off >= 1; off >>= 1)
                mt = fmaxf(mt, __shfl_xor_sync(0xffffffffu, mt, off));
            float mnew = fmaxf(m_i[i], mt);
            float p0 = __expf(s0 - mnew), p1 = __expf(s1 - mnew);
            float p2 = __expf(s2 - mnew), p3 = __expf(s3 - mnew);
            float lt = (p0 + p1) + (p2 + p3);
            #pragma unroll
            for (int off = 8; off >= 1; off >>= 1)
                lt += __shfl_xor_sync(0xffffffffu, lt, off);
            float alpha = __expf(m_i[i] - mnew);
            l_i[i] = l_i[i] * alpha + lt;
            m_i[i] = mnew;
            #pragma unroll
            for (int j = 0; j < 4; j++) acc[i][j] *= alpha;
            float* prow = &Ps[(ty * 4 + i) * FPAD + tx * 4];
            prow[0] = p0; prow[1] = p1; prow[2] = p2; prow[3] = p3;
        }
        __syncthreads();

        // O += P @ V
        #pragma unroll
        for (int j = 0; j < 64; j++) {
            float a[4], b[4];
            #pragma unroll
            for (int i = 0; i < 4; i++) a[i] = Ps[(ty * 4 + i) * FPAD + j];
            #pragma unroll
            for (int c = 0; c < 4; c++) b[c] = Vs[j * FPAD + tx * 4 + c];
            #pragma unroll
            for (int i = 0; i < 4; i++)
                #pragma unroll
                for (int c = 0; c < 4; c++) acc[i][c] = fmaf(a[i], b[c], acc[i][c]);
        }
    }

    #pragma unroll
    for (int i = 0; i < 4; i++) {
        float inv = 1.0f / l_i[i];
        int r = qrow0 + ty * 4 + i;
        #pragma unroll
        for (int j = 0; j < 4; j++)
            o[(size_t)r * D + hcol + tx * 4 + j] = acc[i][j] * inv;
    }
}

// ---------------- fused residual + LayerNorm ----------------
__global__ void add_ln(const float* __restrict__ hin, const float* __restrict__ t,
                       const float* __restrict__ g, const float* __restrict__ b,
                       float* __restrict__ hout)
{
    int row = blockIdx.x, tid = threadIdx.x;  // 128 threads
    float val = hin[(size_t)row * D + tid] + t[(size_t)row * D + tid];
    float s = val, s2 = val * val;
    #pragma unroll
    for (int off = 16; off >= 1; off >>= 1) {
        s  += __shfl_xor_sync(0xffffffffu, s,  off);
        s2 += __shfl_xor_sync(0xffffffffu, s2, off);
    }
    __shared__ float red[8];
    int warp = tid >> 5, lane = tid & 31;
    if (lane == 0) { red[warp] = s; red[4 + warp] = s2; }
    __syncthreads();
    s  = red[0] + red[1] + red[2] + red[3];
    s2 = red[4] + red[5] + red[6] + red[7];
    float mean = s * (1.0f / D);
    float var  = s2 * (1.0f / D) - mean * mean;
    float inv  = rsqrtf(var + EPS);
    hout[(size_t)row * D + tid] = (val - mean) * inv * g[tid] + b[tid];
}

// ---------------- hypergraph conv pieces ----------------
__global__ void zero_kernel(float* p, int n)
{
    int i = blockIdx.x * blockDim.x + threadIdx.x;
    if (i < n) p[i] = 0.0f;
}

__global__ void degree_kernel(const void* __restrict__ edge,
                              float* __restrict__ bdeg, float* __restrict__ ddeg)
{
    int i = blockIdx.x * blockDim.x + threadIdx.x;
    if (i < NNZ) {
        int2 ne = load_edge(edge, i);
        if ((unsigned)ne.x < N && (unsigned)ne.y < NE) {
            atomicAdd(&ddeg[ne.x], 1.0f);
            atomicAdd(&bdeg[ne.y], 1.0f);
        }
    }
}

// one warp per nnz; each lane handles 4 dims (float4 payload, broadcast index)
__global__ void scatter_node_to_edge(const void* __restrict__ edge,
                                     const float* __restrict__ xt, float* __restrict__ e)
{
    int i = blockIdx.x * blockDim.x + threadIdx.x;   // NNZ*32 threads
    int nz = i >> 5, lane = i & 31;
    int2 ne = load_edge(edge, nz);
    if ((unsigned)ne.x >= N || (unsigned)ne.y >= NE) return;
    float4 p = *(const float4*)&xt[(size_t)ne.x * D + lane * 4];
    float* dst = &e[(size_t)ne.y * D + lane * 4];
    atomicAdd(dst + 0, p.x);
    atomicAdd(dst + 1, p.y);
    atomicAdd(dst + 2, p.z);
    atomicAdd(dst + 3, p.w);
}

__global__ void scale_by_bdeg(float* __restrict__ e, const float* __restrict__ bdeg)
{
    int i = blockIdx.x * blockDim.x + threadIdx.x;  // over NE*D
    int row = i >> 7;
    float bd = bdeg[row];
    e[i] *= (bd > 0.0f) ? (1.0f / bd) : 0.0f;
}

__global__ void scatter_edge_to_node(const void* __restrict__ edge,
                                     const float* __restrict__ e, float* __restrict__ out)
{
    int i = blockIdx.x * blockDim.x + threadIdx.x;   // NNZ*32 threads
    int nz = i >> 5, lane = i & 31;
    int2 ne = load_edge(edge, nz);
    if ((unsigned)ne.x >= N || (unsigned)ne.y >= NE) return;
    float4 p = *(const float4*)&e[(size_t)ne.y * D + lane * 4];
    float* dst = &out[(size_t)ne.x * D + lane * 4];
    atomicAdd(dst + 0, p.x);
    atomicAdd(dst + 1, p.y);
    atomicAdd(dst + 2, p.z);
    atomicAdd(dst + 3, p.w);
}

__global__ void finalize_kernel(float* __restrict__ out, const float* __restrict__ ddeg,
                                const float* __restrict__ bh)
{
    int i = blockIdx.x * blockDim.x + threadIdx.x;  // over N*D
    int row = i >> 7, d = i & 127;
    float dd = ddeg[row];
    float v = out[i] * ((dd > 0.0f) ? (1.0f / dd) : 0.0f) + bh[d];
    out[i] = fmaxf(v, 0.0f);
}

// ---------------- launch ----------------
extern "C" void kernel_launch(void* const* d_in, const int* in_sizes, int n_in,
                              void* d_out, int out_size)
{
    const float* x    = (const float*)d_in[0];
    const void*  edge = d_in[1];
    const float* Wq = (const float*)d_in[2],  *bq  = (const float*)d_in[3];
    const float* Wk = (const float*)d_in[4],  *bk  = (const float*)d_in[5];
    const float* Wv = (const float*)d_in[6],  *bv  = (const float*)d_in[7];
    const float* Wo = (const float*)d_in[8],  *bo  = (const float*)d_in[9];
    const float* g1 = (const float*)d_in[10], *b1  = (const float*)d_in[11];
    const float* W1 = (const float*)d_in[12], *bf1 = (const float*)d_in[13];
    const float* W2 = (const float*)d_in[14], *bf2 = (const float*)d_in[15];
    const float* g2 = (const float*)d_in[16], *b2  = (const float*)d_in[17];
    const float* Wh = (const float*)d_in[18], *bh  = (const float*)d_in[19];
    float* out = (float*)d_out;

    float *h, *q, *k, *v, *o, *t, *z, *e, *bdeg, *ddeg;
    cudaGetSymbolAddress((void**)&h, g_h);
    cudaGetSymbolAddress((void**)&q, g_q);
    cudaGetSymbolAddress((void**)&k, g_k);
    cudaGetSymbolAddress((void**)&v, g_v);
    cudaGetSymbolAddress((void**)&o, g_o);
    cudaGetSymbolAddress((void**)&t, g_t);
    cudaGetSymbolAddress((void**)&z, g_z);
    cudaGetSymbolAddress((void**)&e, g_e);
    cudaGetSymbolAddress((void**)&bdeg, g_bdeg);
    cudaGetSymbolAddress((void**)&ddeg, g_ddeg);

    const int FSMEM = 4 * 64 * FPAD * (int)sizeof(float);  // 66560 B
    cudaFuncSetAttribute(flash_attn, cudaFuncAttributeMaxDynamicSharedMemorySize, FSMEM);

    detect_edge_kernel<<<1, 32>>>((const int*)edge);

    dim3 gD(D / 64, N / 64);    // Nc=128
    dim3 gF(FF / 64, N / 64);   // Nc=256

    for (int it = 0; it < 2; ++it) {
        const float* hin = (it == 0) ? x : h;
        sgemm_bias_act<<<gD, 256>>>(hin, Wq, bq, q, N, D, D, 0);
        sgemm_bias_act<<<gD, 256>>>(hin, Wk, bk, k, N, D, D, 0);
        sgemm_bias_act<<<gD, 256>>>(hin, Wv, bv, v, N, D, D, 0);
        flash_attn<<<dim3(N / 64, H), 256, FSMEM>>>(q, k, v, o);
        sgemm_bias_act<<<gD, 256>>>(o, Wo, bo, t, N, D, D, 0);
        add_ln<<<N, 128>>>(hin, t, g1, b1, h);
        sgemm_bias_act<<<gF, 256>>>(h, W1, bf1, z, N, FF, D, 1);
        sgemm_bias_act<<<gD, 256>>>(z, W2, bf2, t, N, D, FF, 0);
        add_ln<<<N, 128>>>(h, t, g2, b2, h);
    }

    // xt = h @ Wh (reuse q buffer)
    sgemm_bias_act<<<gD, 256>>>(h, Wh, nullptr, q, N, D, D, 0);

    zero_kernel<<<(NE * D + 255) / 256, 256>>>(e, NE * D);
    zero_kernel<<<(NE + 255) / 256, 256>>>(bdeg, NE);
    zero_kernel<<<(N + 255) / 256, 256>>>(ddeg, N);
    zero_kernel<<<(N * D + 255) / 256, 256>>>(out, N * D);

    degree_kernel<<<NNZ / 256, 256>>>(edge, bdeg, ddeg);
    scatter_node_to_edge<<<(NNZ * 32) / 256, 256>>>(edge, q, e);
    scale_by_bdeg<<<(NE * D) / 256, 256>>>(e, bdeg);
    scatter_edge_to_node<<<(NNZ * 32) / 256, 256>>>(edge, e, out);
    finalize_kernel<<<(N * D) / 256, 256>>>(out, ddeg, bh);
}

// round 4
// speedup vs baseline: 1.1242x; 1.1242x over previous
#include <cuda_runtime.h>
#include <cuda_bf16.h>
#include <math.h>

#define N   4096
#define D   128
#define H   2
#define DH  64
#define FF  256
#define NE  2048
#define NNZ 65536
#define EPS 1e-5f

typedef unsigned long long u64;

// ---------------- packed f32x2 helpers ----------------
__device__ __forceinline__ u64 pack2(float lo, float hi) {
    u64 r; asm("mov.b64 %0, {%1, %2};" : "=l"(r) : "f"(lo), "f"(hi)); return r;
}
__device__ __forceinline__ void unpack2(u64 p, float& lo, float& hi) {
    asm("mov.b64 {%0, %1}, %2;" : "=f"(lo), "=f"(hi) : "l"(p));
}
__device__ __forceinline__ void fma2(u64& d, u64 a, u64 b) {
    asm("fma.rn.f32x2 %0, %1, %2, %0;" : "+l"(d) : "l"(a), "l"(b));
}
__device__ __forceinline__ void mul2(u64& d, u64 a) {
    asm("mul.rn.f32x2 %0, %0, %1;" : "+l"(d) : "l"(a));
}

// ---------------- scratch (no allocation allowed) ----------------
__device__ float g_h[N * D];
__device__ float g_q[N * D];
__device__ float g_k[N * D];
__device__ float g_v[N * D];
__device__ float g_o[N * D];
__device__ float g_t[N * D];
__device__ float g_z[N * FF];
__device__ float g_e[NE * D];
__device__ float g_bdeg[NE];
__device__ float g_ddeg[N];
__device__ int   g_edge_is64;

// ---------------- edge dtype detection ----------------
__global__ void detect_edge_kernel(const int* __restrict__ e32)
{
    if (threadIdx.x == 0 && blockIdx.x == 0) {
        int is64 = 1;
        #pragma unroll
        for (int i = 1; i < 64; i += 2)
            if (e32[i] != 0) is64 = 0;
        g_edge_is64 = is64;
    }
}

__device__ __forceinline__ int2 load_edge(const void* __restrict__ edge, int nz)
{
    if (g_edge_is64) {
        const long long* e = (const long long*)edge;
        return make_int2((int)e[nz], (int)e[NNZ + nz]);
    } else {
        const int* e = (const int*)edge;
        return make_int2(e[nz], e[NNZ + nz]);
    }
}

// ---------------- tiled SGEMM core (64x64 tile, KC=32, f32x2) ----------------
#define APAD 68
struct GemmSmem { float As[32 * APAD]; float Bs[32 * 64]; };

__device__ __forceinline__ void gemm_tile(const float* __restrict__ A,
                                          const float* __restrict__ B,
                                          const float* __restrict__ bias,
                                          float* __restrict__ C,
                                          int Nc, int K, int act,
                                          int row0, int col0, GemmSmem& sm)
{
    int tid = threadIdx.x;            // 256 threads
    int tx = tid & 15, ty = tid >> 4;

    u64 acc2[4][2] = {};
    for (int k0 = 0; k0 < K; k0 += 32) {
        #pragma unroll
        for (int i = tid; i < 64 * 32; i += 256) {
            int m = i >> 5, kk = i & 31;
            sm.As[kk * APAD + m] = A[(size_t)(row0 + m) * K + k0 + kk];
        }
        #pragma unroll
        for (int i = tid; i < 32 * 64; i += 256) {
            int kk = i >> 6, n = i & 63;
            sm.Bs[kk * 64 + n] = B[(size_t)(k0 + kk) * Nc + col0 + n];
        }
        __syncthreads();
        #pragma unroll
        for (int kk = 0; kk < 32; kk++) {
            float4 a4 = *(const float4*)&sm.As[kk * APAD + ty * 4];
            float4 b4 = *(const float4*)&sm.Bs[kk * 64 + tx * 4];
            u64 b01 = pack2(b4.x, b4.y), b23 = pack2(b4.z, b4.w);
            u64 a0 = pack2(a4.x, a4.x), a1 = pack2(a4.y, a4.y);
            u64 a2 = pack2(a4.z, a4.z), a3 = pack2(a4.w, a4.w);
            fma2(acc2[0][0], a0, b01); fma2(acc2[0][1], a0, b23);
            fma2(acc2[1][0], a1, b01); fma2(acc2[1][1], a1, b23);
            fma2(acc2[2][0], a2, b01); fma2(acc2[2][1], a2, b23);
            fma2(acc2[3][0], a3, b01); fma2(acc2[3][1], a3, b23);
        }
        __syncthreads();
    }
    #pragma unroll
    for (int i = 0; i < 4; i++) {
        int r = row0 + ty * 4 + i;
        float vv[4];
        unpack2(acc2[i][0], vv[0], vv[1]);
        unpack2(acc2[i][1], vv[2], vv[3]);
        #pragma unroll
        for (int j = 0; j < 4; j++) {
            int c = col0 + tx * 4 + j;
            float val = vv[j] + (bias ? bias[c] : 0.0f);
            if (act == 1) val = 1.0f / (1.0f + __expf(-val));
            C[(size_t)r * Nc + c] = val;
        }
    }
}

__global__ void sgemm_bias_act(const float* __restrict__ A, const float* __restrict__ B,
                               const float* __restrict__ bias, float* __restrict__ C,
                               int Nc, int K, int act)
{
    __shared__ GemmSmem sm;
    gemm_tile(A, B, bias, C, Nc, K, act, blockIdx.y * 64, blockIdx.x * 64, sm);
}

// fused QKV: blockIdx.z picks which projection
__global__ void qkv_gemm(const float* __restrict__ A,
                         const float* __restrict__ Wq, const float* __restrict__ bq,
                         const float* __restrict__ Wk, const float* __restrict__ bk,
                         const float* __restrict__ Wv, const float* __restrict__ bv,
                         float* __restrict__ q, float* __restrict__ k, float* __restrict__ v)
{
    __shared__ GemmSmem sm;
    const float* B; const float* bias; float* C;
    if (blockIdx.z == 0)      { B = Wq; bias = bq; C = q; }
    else if (blockIdx.z == 1) { B = Wk; bias = bk; C = k; }
    else                      { B = Wv; bias = bv; C = v; }
    gemm_tile(A, B, bias, C, D, D, 0, blockIdx.y * 64, blockIdx.x * 64, sm);
}

// ---------------- flash attention, fp32+f32x2, BM=BN=64, DH=64 ----------------
#define QP 68
__global__ void flash_attn(const float* __restrict__ q, const float* __restrict__ k,
                           const float* __restrict__ v, float* __restrict__ o)
{
    extern __shared__ float fsm[];
    float* Qs = fsm;              // [d][r]  64 x QP
    float* Ks = Qs + 64 * QP;     // [d][c]
    float* Vs = Ks + 64 * QP;     // [j][c]
    float* Ps = Vs + 64 * QP;     // [r][j]

    int tid = threadIdx.x;            // 256
    int tx = tid & 15, ty = tid >> 4;
    int qrow0 = blockIdx.x * 64;
    int hcol  = blockIdx.y * DH;

    #pragma unroll
    for (int i = tid; i < 64 * 64; i += 256) {
        int r = i >> 6, d = i & 63;
        Qs[d * QP + r] = q[(size_t)(qrow0 + r) * D + hcol + d];
    }

    float m_i[4], l_i[4];
    u64 o2[4][4] = {};       // packed-j partial sums
    #pragma unroll
    for (int i = 0; i < 4; i++) { m_i[i] = -1e30f; l_i[i] = 0.0f; }
    const float scale = 0.125f;  // 1/sqrt(64)

    for (int kb = 0; kb < N; kb += 64) {
        __syncthreads();
        #pragma unroll
        for (int i = tid; i < 64 * 64; i += 256) {
            int c = i >> 6, d = i & 63;
            Ks[d * QP + c] = k[(size_t)(kb + c) * D + hcol + d];
            Vs[c * QP + d] = v[(size_t)(kb + c) * D + hcol + d];
        }
        __syncthreads();

        // S = Q @ K^T  (packed along j)
        u64 s2[4][2] = {};
        #pragma unroll
        for (int d = 0; d < 64; d++) {
            float4 a4 = *(const float4*)&Qs[d * QP + ty * 4];
            float4 b4 = *(const float4*)&Ks[d * QP + tx * 4];
            u64 b01 = pack2(b4.x, b4.y), b23 = pack2(b4.z, b4.w);
            u64 a0 = pack2(a4.x, a4.x), a1 = pack2(a4.y, a4.y);
            u64 a2 = pack2(a4.z, a4.z), a3 = pack2(a4.w, a4.w);
            fma2(s2[0][0], a0, b01); fma2(s2[0][1], a0, b23);
            fma2(s2[1][0], a1, b01); fma2(s2[1][1], a1, b23);
            fma2(s2[2][0], a2, b01); fma2(s2[2][1], a2, b23);
            fma2(s2[3][0], a3, b01); fma2(s2[3][1], a3, b23);
        }

        // online softmax (16-lane row groups share ty)
        #pragma unroll
        for (int i = 0; i < 4; i++) {
            float s0, s1, s2v, s3v;
            unpack2(s2[i][0], s0, s1);
            unpack2(s2[i][1], s2v, s3v);
            s0 *= scale; s1 *= scale; s2v *= scale; s3v *= scale;
            float mt = fmaxf(fmaxf(s0, s1), fmaxf(s2v, s3v));
            #pragma unroll
            for (int off = 8; off >= 1; off >>= 1)
                mt = fmaxf(mt, __shfl_xor_sync(0xffffffffu, mt, off));
            float mnew = fmaxf(m_i[i], mt);
            float p0 = __expf(s0 - mnew), p1 = __expf(s1 - mnew);
            float p2 = __expf(s2v - mnew), p3 = __expf(s3v - mnew);
            float lt = (p0 + p1) + (p2 + p3);
            #pragma unroll
            for (int off = 8; off >= 1; off >>= 1)
                lt += __shfl_xor_sync(0xffffffffu, lt, off);
            float alpha = __expf(m_i[i] - mnew);
            l_i[i] = l_i[i] * alpha + lt;
            m_i[i] = mnew;
            u64 al = pack2(alpha, alpha);
            #pragma unroll
            for (int c = 0; c < 4; c++) mul2(o2[i][c], al);
            float4 pv = make_float4(p0, p1, p2, p3);
            *(float4*)&Ps[(ty * 4 + i) * QP + tx * 4] = pv;
        }
        __syncthreads();

        // O += P @ V  (packed along j: o2 holds pairwise partial sums)
        #pragma unroll
        for (int j = 0; j < 64; j += 2) {
            u64 a2v[4];
            #pragma unroll
            for (int i = 0; i < 4; i++)
                a2v[i] = *(const u64*)&Ps[(ty * 4 + i) * QP + j];
            float4 bj  = *(const float4*)&Vs[j * QP + tx * 4];
            float4 bj1 = *(const float4*)&Vs[(j + 1) * QP + tx * 4];
            u64 bx = pack2(bj.x, bj1.x), by = pack2(bj.y, bj1.y);
            u64 bz = pack2(bj.z, bj1.z), bw = pack2(bj.w, bj1.w);
            #pragma unroll
            for (int i = 0; i < 4; i++) {
                fma2(o2[i][0], a2v[i], bx);
                fma2(o2[i][1], a2v[i], by);
                fma2(o2[i][2], a2v[i], bz);
                fma2(o2[i][3], a2v[i], bw);
            }
        }
    }

    #pragma unroll
    for (int i = 0; i < 4; i++) {
        float inv = 1.0f / l_i[i];
        int r = qrow0 + ty * 4 + i;
        #pragma unroll
        for (int c = 0; c < 4; c++) {
            float lo, hi;
            unpack2(o2[i][c], lo, hi);
            o[(size_t)r * D + hcol + tx * 4 + c] = (lo + hi) * inv;
        }
    }
}

// ---------------- fused residual + LayerNorm ----------------
__global__ void add_ln(const float* __restrict__ hin, const float* __restrict__ t,
                       const float* __restrict__ g, const float* __restrict__ b,
                       float* __restrict__ hout)
{
    int row = blockIdx.x, tid = threadIdx.x;  // 128 threads
    float val = hin[(size_t)row * D + tid] + t[(size_t)row * D + tid];
    float s = val, s2 = val * val;
    #pragma unroll
    for (int off = 16; off >= 1; off >>= 1) {
        s  += __shfl_xor_sync(0xffffffffu, s,  off);
        s2 += __shfl_xor_sync(0xffffffffu, s2, off);
    }
    __shared__ float red[8];
    int warp = tid >> 5, lane = tid & 31;
    if (lane == 0) { red[warp] = s; red[4 + warp] = s2; }
    __syncthreads();
    s  = red[0] + red[1] + red[2] + red[3];
    s2 = red[4] + red[5] + red[6] + red[7];
    float mean = s * (1.0f / D);
    float var  = s2 * (1.0f / D) - mean * mean;
    float inv  = rsqrtf(var + EPS);
    hout[(size_t)row * D + tid] = (val - mean) * inv * g[tid] + b[tid];
}

// ---------------- hypergraph conv pieces ----------------
__global__ void zero_kernel(float* p, int n)
{
    int i = blockIdx.x * blockDim.x + threadIdx.x;
    if (i < n) p[i] = 0.0f;
}

__global__ void degree_kernel(const void* __restrict__ edge,
                              float* __restrict__ bdeg, float* __restrict__ ddeg)
{
    int i = blockIdx.x * blockDim.x + threadIdx.x;
    if (i < NNZ) {
        int2 ne = load_edge(edge, i);
        if ((unsigned)ne.x < N && (unsigned)ne.y < NE) {
            atomicAdd(&ddeg[ne.x], 1.0f);
            atomicAdd(&bdeg[ne.y], 1.0f);
        }
    }
}

__global__ void scatter_node_to_edge(const void* __restrict__ edge,
                                     const float* __restrict__ xt, float* __restrict__ e)
{
    int i = blockIdx.x * blockDim.x + threadIdx.x;   // NNZ*32 threads
    int nz = i >> 5, lane = i & 31;
    int2 ne = load_edge(edge, nz);
    if ((unsigned)ne.x >= N || (unsigned)ne.y >= NE) return;
    float4 p = *(const float4*)&xt[(size_t)ne.x * D + lane * 4];
    float* dst = &e[(size_t)ne.y * D + lane * 4];
    atomicAdd(dst + 0, p.x);
    atomicAdd(dst + 1, p.y);
    atomicAdd(dst + 2, p.z);
    atomicAdd(dst + 3, p.w);
}

__global__ void scale_by_bdeg(float* __restrict__ e, const float* __restrict__ bdeg)
{
    int i = blockIdx.x * blockDim.x + threadIdx.x;  // over NE*D
    int row = i >> 7;
    float bd = bdeg[row];
    e[i] *= (bd > 0.0f) ? (1.0f / bd) : 0.0f;
}

__global__ void scatter_edge_to_node(const void* __restrict__ edge,
                                     const float* __restrict__ e, float* __restrict__ out)
{
    int i = blockIdx.x * blockDim.x + threadIdx.x;   // NNZ*32 threads
    int nz = i >> 5, lane = i & 31;
    int2 ne = load_edge(edge, nz);
    if ((unsigned)ne.x >= N || (unsigned)ne.y >= NE) return;
    float4 p = *(const float4*)&e[(size_t)ne.y * D + lane * 4];
    float* dst = &out[(size_t)ne.x * D + lane * 4];
    atomicAdd(dst + 0, p.x);
    atomicAdd(dst + 1, p.y);
    atomicAdd(dst + 2, p.z);
    atomicAdd(dst + 3, p.w);
}

__global__ void finalize_kernel(float* __restrict__ out, const float* __restrict__ ddeg,
                                const float* __restrict__ bh)
{
    int i = blockIdx.x * blockDim.x + threadIdx.x;  // over N*D
    int row = i >> 7, d = i & 127;
    float dd = ddeg[row];
    float v = out[i] * ((dd > 0.0f) ? (1.0f / dd) : 0.0f) + bh[d];
    out[i] = fmaxf(v, 0.0f);
}

// ---------------- launch ----------------
extern "C" void kernel_launch(void* const* d_in, const int* in_sizes, int n_in,
                              void* d_out, int out_size)
{
    const float* x    = (const float*)d_in[0];
    const void*  edge = d_in[1];
    const float* Wq = (const float*)d_in[2],  *bq  = (const float*)d_in[3];
    const float* Wk = (const float*)d_in[4],  *bk  = (const float*)d_in[5];
    const float* Wv = (const float*)d_in[6],  *bv  = (const float*)d_in[7];
    const float* Wo = (const float*)d_in[8],  *bo  = (const float*)d_in[9];
    const float* g1 = (const float*)d_in[10], *b1  = (const float*)d_in[11];
    const float* W1 = (const float*)d_in[12], *bf1 = (const float*)d_in[13];
    const float* W2 = (const float*)d_in[14], *bf2 = (const float*)d_in[15];
    const float* g2 = (const float*)d_in[16], *b2  = (const float*)d_in[17];
    const float* Wh = (const float*)d_in[18], *bh  = (const float*)d_in[19];
    float* out = (float*)d_out;

    float *h, *q, *k, *v, *o, *t, *z, *e, *bdeg, *ddeg;
    cudaGetSymbolAddress((void**)&h, g_h);
    cudaGetSymbolAddress((void**)&q, g_q);
    cudaGetSymbolAddress((void**)&k, g_k);
    cudaGetSymbolAddress((void**)&v, g_v);
    cudaGetSymbolAddress((void**)&o, g_o);
    cudaGetSymbolAddress((void**)&t, g_t);
    cudaGetSymbolAddress((void**)&z, g_z);
    cudaGetSymbolAddress((void**)&e, g_e);
    cudaGetSymbolAddress((void**)&bdeg, g_bdeg);
    cudaGetSymbolAddress((void**)&ddeg, g_ddeg);

    const int FSMEM = 4 * 64 * QP * (int)sizeof(float);  // 69632 B
    cudaFuncSetAttribute(flash_attn, cudaFuncAttributeMaxDynamicSharedMemorySize, FSMEM);

    detect_edge_kernel<<<1, 32>>>((const int*)edge);

    dim3 gD(D / 64, N / 64);       // 2 x 64
    dim3 gF(FF / 64, N / 64);      // 4 x 64
    dim3 gQKV(D / 64, N / 64, 3);  // 2 x 64 x 3

    for (int it = 0; it < 2; ++it) {
        const float* hin = (it == 0) ? x : h;
        qkv_gemm<<<gQKV, 256>>>(hin, Wq, bq, Wk, bk, Wv, bv, q, k, v);
        flash_attn<<<dim3(N / 64, H), 256, FSMEM>>>(q, k, v, o);
        sgemm_bias_act<<<gD, 256>>>(o, Wo, bo, t, D, D, 0);
        add_ln<<<N, 128>>>(hin, t, g1, b1, h);
        sgemm_bias_act<<<gF, 256>>>(h, W1, bf1, z, FF, D, 1);
        sgemm_bias_act<<<gD, 256>>>(z, W2, bf2, t, D, FF, 0);
        add_ln<<<N, 128>>>(h, t, g2, b2, h);
    }

    // xt = h @ Wh (reuse q buffer)
    sgemm_bias_act<<<gD, 256>>>(h, Wh, nullptr, q, D, D, 0);

    zero_kernel<<<(NE * D + 255) / 256, 256>>>(e, NE * D);
    zero_kernel<<<(NE + 255) / 256, 256>>>(bdeg, NE);
    zero_kernel<<<(N + 255) / 256, 256>>>(ddeg, N);
    zero_kernel<<<(N * D + 255) / 256, 256>>>(out, N * D);

    degree_kernel<<<NNZ / 256, 256>>>(edge, bdeg, ddeg);
    scatter_node_to_edge<<<(NNZ * 32) / 256, 256>>>(edge, q, e);
    scale_by_bdeg<<<(NE * D) / 256, 256>>>(e, bdeg);
    scatter_edge_to_node<<<(NNZ * 32) / 256, 256>>>(edge, e, out);
    finalize_kernel<<<(N * D) / 256, 256>>>(out, ddeg, bh);
}